// round 1
// baseline (speedup 1.0000x reference)
#include <cuda_runtime.h>

#define BS 2
#define NPTS 65536
#define KNN 16
#define CH 16
#define CO 32
#define NK (BS*NPTS*KNN)
#define NP (BS*NPTS)
#define EPSV 1e-5f
#define SLOPE 0.2f

// ---------------- scratch (no cudaMalloc allowed) ----------------
__device__ float4 g_xyzT[NP];          // [b*N+n] = {x,y,z,0}
__device__ float  g_featT[NP*CH];      // [b*N+n][16]
__device__ float  g_z1[NP*CH];         // stage1 pre-BN pooled output
__device__ float  g_z2[NP*CO];         // stage2 pre-BN pooled output
__device__ float  g_acc[192];          // stat sums
__device__ float  g_bnp[192];          // finalized BN scale/shift

typedef unsigned long long u64;

__device__ __forceinline__ u64 pack2(float lo, float hi){
    u64 r; asm("mov.b64 %0, {%1,%2};" : "=l"(r) : "f"(lo), "f"(hi)); return r;
}
__device__ __forceinline__ void fma2(u64 &d, u64 a, u64 b){
    asm("fma.rn.f32x2 %0, %1, %2, %3;" : "=l"(d) : "l"(a), "l"(b), "l"(d));
}
__device__ __forceinline__ float lohi_sum(u64 v){
    float lo, hi; asm("mov.b64 {%0,%1}, %2;" : "=f"(lo), "=f"(hi) : "l"(v)); return lo + hi;
}
__device__ __forceinline__ float lrelu(float x){ return x >= 0.f ? x : SLOPE * x; }
__device__ __forceinline__ float wsum(float v){
    #pragma unroll
    for (int o = 16; o; o >>= 1) v += __shfl_down_sync(0xffffffffu, v, o);
    return v;
}

// ---------------- transpose xyz + feature, zero accumulators ----------------
__global__ void k_t01(const float* __restrict__ xyz, const float* __restrict__ feat){
    int i = blockIdx.x * blockDim.x + threadIdx.x;   // b*N+n, grid exactly covers NP
    if (blockIdx.x == 0 && threadIdx.x < 192) g_acc[threadIdx.x] = 0.f;
    int b = i >> 16, n = i & 65535;
    const float* xp = xyz + b * 3 * NPTS;
    g_xyzT[i] = make_float4(xp[n], xp[NPTS + n], xp[2 * NPTS + n], 0.f);
    const float* fp = feat + b * CH * NPTS;
    #pragma unroll
    for (int c = 0; c < CH; c++) g_featT[i * CH + c] = fp[c * NPTS + n];
}

// ---------------- stats of y1 = W1 @ fxyz + b1 over (b,n,k) ----------------
__global__ void k_stats1(const int* __restrict__ nidx, const float* __restrict__ w1,
                         const float* __restrict__ b1){
    __shared__ float W1s[160], b1s[16], sS[16], ssS[16];
    int t = threadIdx.x;
    if (t < 160) W1s[t] = w1[t];
    if (t < 16){ b1s[t] = b1[t]; sS[t] = 0.f; ssS[t] = 0.f; }
    __syncthreads();
    float s[16], ss[16];
    #pragma unroll
    for (int c = 0; c < 16; c++){ s[c] = 0.f; ss[c] = 0.f; }
    int T = gridDim.x * blockDim.x;
    for (int e = blockIdx.x * blockDim.x + t; e < NK; e += T){
        int id = nidx[e];
        int p = e >> 4, b = e >> 20;
        float4 cc = g_xyzT[p];
        float4 nb = g_xyzT[(b << 16) + id];
        float rx = cc.x - nb.x, ry = cc.y - nb.y, rz = cc.z - nb.z;
        float dis = sqrtf(rx*rx + ry*ry + rz*rz);
        #pragma unroll
        for (int c = 0; c < 16; c++){
            const float* w = W1s + c * 10;
            float y = b1s[c] + w[0]*dis + w[1]*rx + w[2]*ry + w[3]*rz
                    + w[4]*cc.x + w[5]*cc.y + w[6]*cc.z + w[7]*nb.x + w[8]*nb.y + w[9]*nb.z;
            s[c] += y; ss[c] += y * y;
        }
    }
    #pragma unroll
    for (int c = 0; c < 16; c++){
        float a = wsum(s[c]), q = wsum(ss[c]);
        if ((t & 31) == 0){ atomicAdd(&sS[c], a); atomicAdd(&ssS[c], q); }
    }
    __syncthreads();
    if (t < 16){ atomicAdd(&g_acc[t], sS[t]); atomicAdd(&g_acc[16 + t], ssS[t]); }
}

// ---------------- stats of y2 = W2 @ lrelu(bn1(y1)) + b2 ----------------
__global__ void k_stats2(const int* __restrict__ nidx, const float* __restrict__ w1,
                         const float* __restrict__ b1, const float* __restrict__ w2,
                         const float* __restrict__ b2){
    __shared__ float W1s[160], b1s[16], sc1[16], sh1[16], W2s[256], b2s[16], sS[16], ssS[16];
    int t = threadIdx.x;
    if (t < 160) W1s[t] = w1[t];
    if (t < 256) W2s[t] = w2[t];
    if (t < 16){ b1s[t]=b1[t]; b2s[t]=b2[t]; sc1[t]=g_bnp[t]; sh1[t]=g_bnp[16+t]; sS[t]=0.f; ssS[t]=0.f; }
    __syncthreads();
    float s[16], ss[16];
    #pragma unroll
    for (int c = 0; c < 16; c++){ s[c]=0.f; ss[c]=0.f; }
    int T = gridDim.x * blockDim.x;
    for (int e = blockIdx.x * blockDim.x + t; e < NK; e += T){
        int id = nidx[e];
        int p = e >> 4, b = e >> 20;
        float4 cc = g_xyzT[p];
        float4 nb = g_xyzT[(b << 16) + id];
        float rx = cc.x - nb.x, ry = cc.y - nb.y, rz = cc.z - nb.z;
        float dis = sqrtf(rx*rx + ry*ry + rz*rz);
        float fx[16];
        #pragma unroll
        for (int c = 0; c < 16; c++){
            const float* w = W1s + c * 10;
            float y = b1s[c] + w[0]*dis + w[1]*rx + w[2]*ry + w[3]*rz
                    + w[4]*cc.x + w[5]*cc.y + w[6]*cc.z + w[7]*nb.x + w[8]*nb.y + w[9]*nb.z;
            fx[c] = lrelu(y * sc1[c] + sh1[c]);
        }
        #pragma unroll
        for (int o = 0; o < 16; o++){
            float y2 = b2s[o];
            #pragma unroll
            for (int j = 0; j < 16; j++) y2 += W2s[o * 16 + j] * fx[j];
            s[o] += y2; ss[o] += y2 * y2;
        }
    }
    #pragma unroll
    for (int c = 0; c < 16; c++){
        float a = wsum(s[c]), q = wsum(ss[c]);
        if ((t & 31) == 0){ atomicAdd(&sS[c], a); atomicAdd(&ssS[c], q); }
    }
    __syncthreads();
    if (t < 16){ atomicAdd(&g_acc[32 + t], sS[t]); atomicAdd(&g_acc[48 + t], ssS[t]); }
}

// ---------------- finalize BN params ----------------
__global__ void k_fin(int accOff, int bnpOff, float inv_cnt, int nch,
                      const float* __restrict__ g, const float* __restrict__ be){
    int c = threadIdx.x;
    if (c < nch){
        float m = g_acc[accOff + c] * inv_cnt;
        float v = g_acc[accOff + nch + c] * inv_cnt - m * m;
        float sc = g[c] * rsqrtf(v + EPSV);
        g_bnp[bnpOff + c] = sc;
        g_bnp[bnpOff + nch + c] = be[c] - m * sc;
    }
}

// ---------------- stage 1: build f_concat, attentive pool, store z1 ----------------
__global__ void __launch_bounds__(256) k_stage1(
        const int* __restrict__ nidx, const float* __restrict__ w1, const float* __restrict__ b1,
        const float* __restrict__ wfc, const float* __restrict__ bfc,
        const float* __restrict__ wap, const float* __restrict__ bap){
    __shared__ float W1s[160], b1s[16], sc1[16], sh1[16], WapT[32*16], baps[16];
    __shared__ __align__(16) float fS[8][16][32];
    __shared__ __align__(16) float aggS[8][32];
    int t = threadIdx.x;
    if (t < 160) W1s[t] = w1[t];
    if (t < 16){ b1s[t]=b1[t]; sc1[t]=g_bnp[t]; sh1[t]=g_bnp[16+t]; baps[t]=bap[t]; }
    for (int i = t; i < 512; i += 256){ int o = i >> 5, c = i & 31; WapT[c * 16 + o] = wap[i]; }
    __syncthreads();
    int lane = t & 31, w = t >> 5, c2 = lane - 16;
    u64 wr2[16];
    #pragma unroll
    for (int j = 0; j < 16; j++) wr2[j] = pack2(wfc[lane * 32 + 2*j], wfc[lane * 32 + 2*j + 1]);
    float bfcl = bfc[lane];
    int warpsTotal = (gridDim.x * blockDim.x) >> 5;
    for (int pid = blockIdx.x * 8 + w; pid < NP; pid += warpsTotal){
        int b = pid >> 16;
        int idxl = (lane < 16) ? nidx[pid * 16 + lane] : 0;
        float4 cc = g_xyzT[pid];
        float f[16];
        #pragma unroll
        for (int k = 0; k < 16; k++){
            int id = __shfl_sync(0xffffffffu, idxl, k);
            float v;
            if (lane < 16){
                v = g_featT[((b << 16) + id) * CH + lane];
            } else {
                float4 nb = g_xyzT[(b << 16) + id];
                float rx = cc.x - nb.x, ry = cc.y - nb.y, rz = cc.z - nb.z;
                float dis = sqrtf(rx*rx + ry*ry + rz*rz);
                const float* wp = W1s + c2 * 10;
                float y = b1s[c2] + wp[0]*dis + wp[1]*rx + wp[2]*ry + wp[3]*rz
                        + wp[4]*cc.x + wp[5]*cc.y + wp[6]*cc.z + wp[7]*nb.x + wp[8]*nb.y + wp[9]*nb.z;
                v = lrelu(y * sc1[c2] + sh1[c2]);
            }
            f[k] = v;
            fS[w][k][lane] = v;
        }
        __syncwarp();
        float att[16];
        #pragma unroll
        for (int k = 0; k < 16; k++){
            const ulonglong2* fp = reinterpret_cast<const ulonglong2*>(&fS[w][k][0]);
            u64 acc = 0ULL;
            #pragma unroll
            for (int i = 0; i < 8; i++){
                ulonglong2 u = fp[i];
                fma2(acc, u.x, wr2[2*i]);
                fma2(acc, u.y, wr2[2*i + 1]);
            }
            att[k] = lohi_sum(acc) + bfcl;
        }
        float m = att[0];
        #pragma unroll
        for (int k = 1; k < 16; k++) m = fmaxf(m, att[k]);
        float s = 0.f, agg = 0.f;
        #pragma unroll
        for (int k = 0; k < 16; k++){ float e = __expf(att[k] - m); s += e; agg += f[k] * e; }
        agg /= s;
        aggS[w][lane] = agg;
        __syncwarp();
        if (lane < 16){
            float z = baps[lane];
            #pragma unroll
            for (int c = 0; c < 32; c++) z += WapT[c * 16 + lane] * aggS[w][c];
            g_z1[pid * CH + lane] = z;
        }
        __syncwarp();
    }
}

// ---------------- stage 2 ----------------
__global__ void __launch_bounds__(256) k_stage2(
        const int* __restrict__ nidx, const float* __restrict__ w1, const float* __restrict__ b1,
        const float* __restrict__ w2, const float* __restrict__ b2,
        const float* __restrict__ wfc, const float* __restrict__ bfc,
        const float* __restrict__ wap, const float* __restrict__ bap){
    __shared__ float W1s[160], b1s[16], sc1[16], sh1[16], sc2[16], sh2[16],
                     scA[16], shA[16], b2s[16], WapT[32*32], baps[32];
    __shared__ __align__(16) float fS[8][16][32];
    __shared__ __align__(16) float fx1S[8][16][16];
    __shared__ __align__(16) float aggS[8][32];
    int t = threadIdx.x;
    if (t < 160) W1s[t] = w1[t];
    if (t < 16){
        b1s[t]=b1[t]; b2s[t]=b2[t];
        sc1[t]=g_bnp[t];    sh1[t]=g_bnp[16+t];
        sc2[t]=g_bnp[32+t]; sh2[t]=g_bnp[48+t];
        scA[t]=g_bnp[64+t]; shA[t]=g_bnp[80+t];
    }
    if (t < 32) baps[t] = bap[t];
    for (int i = t; i < 1024; i += 256){ int o = i >> 5, c = i & 31; WapT[c * 32 + o] = wap[i]; }
    __syncthreads();
    int lane = t & 31, w = t >> 5, c2 = lane - 16;
    u64 wr2[16];
    #pragma unroll
    for (int j = 0; j < 16; j++) wr2[j] = pack2(wfc[lane * 32 + 2*j], wfc[lane * 32 + 2*j + 1]);
    float bfcl = bfc[lane];
    u64 w2r2[8];
    #pragma unroll
    for (int j = 0; j < 8; j++)
        w2r2[j] = (lane >= 16) ? pack2(w2[c2 * 16 + 2*j], w2[c2 * 16 + 2*j + 1]) : 0ULL;
    int warpsTotal = (gridDim.x * blockDim.x) >> 5;
    for (int pid = blockIdx.x * 8 + w; pid < NP; pid += warpsTotal){
        int b = pid >> 16;
        int idxl = (lane < 16) ? nidx[pid * 16 + lane] : 0;
        float4 cc = g_xyzT[pid];
        float f[16];
        #pragma unroll
        for (int k = 0; k < 16; k++){
            int id = __shfl_sync(0xffffffffu, idxl, k);
            if (lane < 16){
                float v = g_z1[((b << 16) + id) * CH + lane];
                v = v * scA[lane] + shA[lane];
                f[k] = lrelu(v);
            } else {
                float4 nb = g_xyzT[(b << 16) + id];
                float rx = cc.x - nb.x, ry = cc.y - nb.y, rz = cc.z - nb.z;
                float dis = sqrtf(rx*rx + ry*ry + rz*rz);
                const float* wp = W1s + c2 * 10;
                float y = b1s[c2] + wp[0]*dis + wp[1]*rx + wp[2]*ry + wp[3]*rz
                        + wp[4]*cc.x + wp[5]*cc.y + wp[6]*cc.z + wp[7]*nb.x + wp[8]*nb.y + wp[9]*nb.z;
                fx1S[w][k][c2] = lrelu(y * sc1[c2] + sh1[c2]);
            }
        }
        __syncwarp();
        if (lane >= 16){
            #pragma unroll
            for (int k = 0; k < 16; k++){
                const ulonglong2* xp = reinterpret_cast<const ulonglong2*>(&fx1S[w][k][0]);
                u64 acc = 0ULL;
                #pragma unroll
                for (int i = 0; i < 4; i++){
                    ulonglong2 u = xp[i];
                    fma2(acc, u.x, w2r2[2*i]);
                    fma2(acc, u.y, w2r2[2*i + 1]);
                }
                float y2 = lohi_sum(acc) + b2s[c2];
                f[k] = lrelu(y2 * sc2[c2] + sh2[c2]);
            }
        }
        #pragma unroll
        for (int k = 0; k < 16; k++) fS[w][k][lane] = f[k];
        __syncwarp();
        float att[16];
        #pragma unroll
        for (int k = 0; k < 16; k++){
            const ulonglong2* fp = reinterpret_cast<const ulonglong2*>(&fS[w][k][0]);
            u64 acc = 0ULL;
            #pragma unroll
            for (int i = 0; i < 8; i++){
                ulonglong2 u = fp[i];
                fma2(acc, u.x, wr2[2*i]);
                fma2(acc, u.y, wr2[2*i + 1]);
            }
            att[k] = lohi_sum(acc) + bfcl;
        }
        float m = att[0];
        #pragma unroll
        for (int k = 1; k < 16; k++) m = fmaxf(m, att[k]);
        float s = 0.f, agg = 0.f;
        #pragma unroll
        for (int k = 0; k < 16; k++){ float e = __expf(att[k] - m); s += e; agg += f[k] * e; }
        agg /= s;
        aggS[w][lane] = agg;
        __syncwarp();
        float z = baps[lane];
        #pragma unroll
        for (int c = 0; c < 32; c++) z += WapT[c * 32 + lane] * aggS[w][c];
        g_z2[pid * CO + lane] = z;
        __syncwarp();
    }
}

// ---------------- channel stats over z buffers ----------------
template<int NCH>
__global__ void k_red(int which, int total, int accOff){
    __shared__ float sS[NCH], ssS[NCH];
    const float* buf = (which == 1) ? g_z1 : g_z2;
    int t = threadIdx.x;
    if (t < NCH){ sS[t] = 0.f; ssS[t] = 0.f; }
    __syncthreads();
    int T = gridDim.x * blockDim.x;
    float s = 0.f, ss = 0.f;
    for (int i = blockIdx.x * blockDim.x + t; i < total; i += T){
        float v = buf[i]; s += v; ss += v * v;
    }
    int c = t % NCH;
    if (NCH == 16){ s += __shfl_xor_sync(0xffffffffu, s, 16); ss += __shfl_xor_sync(0xffffffffu, ss, 16); }
    if ((t & 31) < NCH){ atomicAdd(&sS[c], s); atomicAdd(&ssS[c], ss); }
    __syncthreads();
    if (t < NCH){ atomicAdd(&g_acc[accOff + t], sS[t]); atomicAdd(&g_acc[accOff + NCH + t], ssS[t]); }
}

// ---------------- final BN+LReLU + transpose to output layout ----------------
__global__ void k_out(float* __restrict__ out){
    __shared__ float tile[32][33];
    int bx = blockIdx.x;
    int b = bx >> 11;
    int n0 = (bx & 2047) << 5;
    int tx = threadIdx.x, ty = threadIdx.y;
    #pragma unroll
    for (int i = 0; i < 4; i++){
        int r = ty + i * 8;
        tile[r][tx] = g_z2[((b << 16) + n0 + r) * CO + tx];
    }
    __syncthreads();
    #pragma unroll
    for (int i = 0; i < 4; i++){
        int c = ty + i * 8;
        float v = tile[tx][c] * g_bnp[96 + c] + g_bnp[128 + c];
        out[(b * CO + c) * NPTS + n0 + tx] = lrelu(v);
    }
}

extern "C" void kernel_launch(void* const* d_in, const int* in_sizes, int n_in,
                              void* d_out, int out_size){
    const float* xyz     = (const float*)d_in[0];
    const float* feature = (const float*)d_in[1];
    const int*   nidx    = (const int*)  d_in[2];
    const float* w_mlp1  = (const float*)d_in[3];
    const float* b_mlp1  = (const float*)d_in[4];
    const float* g_mlp1  = (const float*)d_in[5];
    const float* be_mlp1 = (const float*)d_in[6];
    const float* w_fc1   = (const float*)d_in[7];
    const float* b_fc1   = (const float*)d_in[8];
    const float* w_ap1   = (const float*)d_in[9];
    const float* b_ap1   = (const float*)d_in[10];
    const float* g_ap1   = (const float*)d_in[11];
    const float* be_ap1  = (const float*)d_in[12];
    const float* w_mlp2  = (const float*)d_in[13];
    const float* b_mlp2  = (const float*)d_in[14];
    const float* g_mlp2  = (const float*)d_in[15];
    const float* be_mlp2 = (const float*)d_in[16];
    const float* w_fc2   = (const float*)d_in[17];
    const float* b_fc2   = (const float*)d_in[18];
    const float* w_ap2   = (const float*)d_in[19];
    const float* b_ap2   = (const float*)d_in[20];
    const float* g_ap2   = (const float*)d_in[21];
    const float* be_ap2  = (const float*)d_in[22];
    float* out = (float*)d_out;

    k_t01<<<512, 256>>>(xyz, feature);
    k_stats1<<<1024, 256>>>(nidx, w_mlp1, b_mlp1);
    k_fin<<<1, 32>>>(0, 0, 1.f / (float)NK, 16, g_mlp1, be_mlp1);
    k_stats2<<<1024, 256>>>(nidx, w_mlp1, b_mlp1, w_mlp2, b_mlp2);
    k_fin<<<1, 32>>>(32, 32, 1.f / (float)NK, 16, g_mlp2, be_mlp2);
    k_stage1<<<1024, 256>>>(nidx, w_mlp1, b_mlp1, w_fc1, b_fc1, w_ap1, b_ap1);
    k_red<16><<<256, 256>>>(1, NP * CH, 64);
    k_fin<<<1, 32>>>(64, 64, 1.f / (float)NP, 16, g_ap1, be_ap1);
    k_stage2<<<1024, 256>>>(nidx, w_mlp1, b_mlp1, w_mlp2, b_mlp2, w_fc2, b_fc2, w_ap2, b_ap2);
    k_red<32><<<256, 256>>>(2, NP * CO, 96);
    k_fin<<<1, 32>>>(96, 96, 1.f / (float)NP, 32, g_ap2, be_ap2);
    dim3 bt(32, 8);
    k_out<<<4096, bt>>>(out);
}